// round 15
// baseline (speedup 1.0000x reference)
#include <cuda_runtime.h>
#include <cuda_pipeline.h>
#include <math.h>

// Shapes
#define Bn 128
#define Tn 64
#define Un 256
#define Vn 48
#define Sn 192
#define CL 8
#define NG 16
#define NGRID 152
#define NTHR 288   // 8 worker warps + 1 control warp

typedef unsigned long long ull;
typedef unsigned int u32;

// ---------------- device globals ----------------
__device__ float    g_proj[(size_t)NG * CL * 8 * Tn * 128];  // [grp][q][r][t][c]
__device__ float    g_embP[CL * Vn * 128];                   // [q][v][c]
__device__ float    g_wC[CL * Un * 128];                     // [q][k][c]
__device__ int      g_ts[Bn];

// ---------------- helpers ----------------
__device__ __forceinline__ ull pack2(float x, float y) {
    ull r; asm("mov.b64 %0, {%1, %2};" : "=l"(r) : "f"(x), "f"(y)); return r;
}
__device__ __forceinline__ void ffma2(ull& d, ull a, ull b) {
    asm("fma.rn.f32x2 %0, %1, %2, %0;" : "+l"(d) : "l"(a), "l"(b));
}
__device__ __forceinline__ ull add2(ull a, ull b) {
    ull r; asm("add.rn.f32x2 %0, %1, %2;" : "=l"(r) : "l"(a), "l"(b)); return r;
}
__device__ __forceinline__ float2 unpack2(ull v) {
    float2 f; asm("mov.b64 {%0, %1}, %2;" : "=f"(f.x), "=f"(f.y) : "l"(v)); return f;
}
__device__ __forceinline__ u32 smem_u32(const void* p) {
    u32 a; asm("{ .reg .u64 t; cvta.to.shared.u64 t, %1; cvt.u32.u64 %0, t; }" : "=r"(a) : "l"(p)); return a;
}
__device__ __forceinline__ u32 mapa_(u32 la, u32 rank) {
    u32 ra; asm("mapa.shared::cluster.u32 %0, %1, %2;" : "=r"(ra) : "r"(la), "r"(rank)); return ra;
}
__device__ __forceinline__ void stc_u32(u32 la, int rank, u32 v) {
    u32 ra = mapa_(la, (u32)rank);
    asm volatile("st.shared::cluster.u32 [%0], %1;" :: "r"(ra), "r"(v));
}
__device__ __forceinline__ u32 ld_vol_sh(u32 addr) {
    u32 v; asm volatile("ld.volatile.shared.u32 %0, [%1];" : "=r"(v) : "r"(addr)); return v;
}
__device__ __forceinline__ void mbar_init_(u32 a, u32 cnt) {
    asm volatile("mbarrier.init.shared.b64 [%0], %1;" :: "r"(a), "r"(cnt) : "memory");
}
__device__ __forceinline__ void mbar_expect_(u32 a, u32 bytes) {
    asm volatile("mbarrier.arrive.expect_tx.shared.b64 _, [%0], %1;" :: "r"(a), "r"(bytes) : "memory");
}
__device__ __forceinline__ void mbar_wait_(u32 a, u32 ph) {
    u32 done;
    asm volatile("{\n\t.reg .pred p;\n\t"
                 "mbarrier.try_wait.parity.acquire.cta.shared::cta.b64 p, [%1], %2;\n\t"
                 "selp.b32 %0, 1, 0, p;\n\t}" : "=r"(done) : "r"(a), "r"(ph) : "memory");
    if (!done) {
        asm volatile("{\n\t.reg .pred P1;\n\t"
                     "WL_%=:\n\t"
                     "mbarrier.try_wait.parity.acquire.cta.shared::cta.b64 P1, [%0], %1, 0x989680;\n\t"
                     "@P1 bra.uni WD_%=;\n\t"
                     "bra.uni WL_%=;\n\t"
                     "WD_%=:\n\t}" :: "r"(a), "r"(ph) : "memory");
    }
}
__device__ __forceinline__ void bulk_dsmem_(u32 dst, u32 src, u32 bytes, u32 mbar) {
    asm volatile("cp.async.bulk.shared::cluster.shared::cta.mbarrier::complete_tx::bytes "
                 "[%0], [%1], %2, [%3];"
                 :: "r"(dst), "r"(src), "r"(bytes), "r"(mbar) : "memory");
}
#define BULK_COMMIT()     asm volatile("cp.async.bulk.commit_group;" ::: "memory")
#define BULK_WAIT_READ0() asm volatile("cp.async.bulk.wait_group.read 0;" ::: "memory")
#define FENCE_ASYNC()     asm volatile("fence.proxy.async.shared::cta;" ::: "memory")
__device__ __forceinline__ float sigm(float x) { return 1.0f / (1.0f + expf(-x)); }

// ---------------- nop (ncu launch alignment) ----------------
__global__ void k_nop() {}

// ---------------- fused prep ----------------
__global__ void k_prep(const int* __restrict__ word_ids,
                       const float* __restrict__ embed,
                       const float* __restrict__ W,
                       const float* __restrict__ bias,
                       const float* __restrict__ Uw) {
    int bi = blockIdx.x, tid = threadIdx.x;
    if (bi == 0) {
        if (tid < Bn) {
            int c = 0;
            for (int t = 0; t < Tn; t++) c += (word_ids[tid * Tn + t] != 0);
            g_ts[tid] = c;
        }
        return;
    }
    if (bi <= 192) {
        int e = bi - 1;
        int t = e >> 2;
        int col = (e & 3) * 256 + tid;
        float acc = bias[col];
        for (int k = 0; k < 256; k++)
            acc += embed[t * 256 + k] * W[k * 1024 + col];
        int unit = col & 255, gate = col >> 8;
        int q = unit >> 5, ul = unit & 31;
        g_embP[(q * Vn + t) * 128 + ul * 4 + gate] = acc;
        return;
    }
    int idx = (bi - 193) * 256 + tid;
    int q = idx >> 15, r = idx & 32767;
    int k = r >> 7, c = r & 127;
    int gate = c & 3, ul = c >> 2;
    int col = gate * 256 + 32 * q + ul;
    g_wC[idx] = Uw[k * 1024 + col];
}

// ---------------- proj GEMM: 128x128 tile, f32x2, cp.async double buffer ----------------
__global__ void __launch_bounds__(256) k_proj(const float* __restrict__ A,
                                              const float* __restrict__ W) {
    __shared__ __align__(16) float As[2][128 * 16];
    __shared__ __align__(16) float Bs[2][16 * 128];
    int row0 = blockIdx.y * 128, col0 = blockIdx.x * 128;
    int tid = threadIdx.x;
    int tr = tid >> 4, tc = tid & 15;
    int lr = tid >> 1, lk = (tid & 1) * 8;
    int lkb = tid >> 4, lcb = (tid & 15) * 8;

    ull acc[8][4];
#pragma unroll
    for (int i = 0; i < 8; i++)
#pragma unroll
        for (int j = 0; j < 4; j++) acc[i][j] = 0ull;

    auto stage = [&](int ks) {
        int buf = ks & 1;
        int k0 = ks * 16;
        __pipeline_memcpy_async(&As[buf][lr * 16 + lk],
                                &A[(size_t)(row0 + lr) * 768 + k0 + lk], 16);
        __pipeline_memcpy_async(&As[buf][lr * 16 + lk + 4],
                                &A[(size_t)(row0 + lr) * 768 + k0 + lk + 4], 16);
        __pipeline_memcpy_async(&Bs[buf][lkb * 128 + lcb],
                                &W[(size_t)(256 + k0 + lkb) * 1024 + col0 + lcb], 16);
        __pipeline_memcpy_async(&Bs[buf][lkb * 128 + lcb + 4],
                                &W[(size_t)(256 + k0 + lkb) * 1024 + col0 + lcb + 4], 16);
        __pipeline_commit();
    };

    stage(0);
    for (int ks = 0; ks < 48; ks++) {
        if (ks < 47) { stage(ks + 1); __pipeline_wait_prior(1); }
        else         { __pipeline_wait_prior(0); }
        __syncthreads();
        int buf = ks & 1;
        const float* Ab = &As[buf][tr * 8 * 16];
        const ull*   Bb = (const ull*)&Bs[buf][tc * 8];
#pragma unroll
        for (int kk = 0; kk < 16; kk++) {
            ulonglong2 b01 = *(const ulonglong2*)(Bb + (size_t)kk * 64);
            ulonglong2 b23 = *(const ulonglong2*)(Bb + (size_t)kk * 64 + 2);
            ull bv[4] = {b01.x, b01.y, b23.x, b23.y};
#pragma unroll
            for (int i = 0; i < 8; i++) {
                float a = Ab[i * 16 + kk];
                ull ap = pack2(a, a);
                ffma2(acc[i][0], ap, bv[0]);
                ffma2(acc[i][1], ap, bv[1]);
                ffma2(acc[i][2], ap, bv[2]);
                ffma2(acc[i][3], ap, bv[3]);
            }
        }
        __syncthreads();
    }

#pragma unroll
    for (int i = 0; i < 8; i++) {
        int row = row0 + tr * 8 + i;
        int b = row >> 6, t = row & 63;
        int g = b >> 3, rr = b & 7;
#pragma unroll
        for (int j = 0; j < 4; j++) {
            float2 v = unpack2(acc[i][j]);
            int col = col0 + tc * 8 + 2 * j;
#pragma unroll
            for (int e = 0; e < 2; e++) {
                int cc = col + e;
                int unit = cc & 255, gate = cc >> 8;
                int q = unit >> 5, ul = unit & 31;
                g_proj[((((size_t)(g * CL + q) * 8 + rr) * Tn + t) * 128) + ul * 4 + gate] =
                    (e == 0) ? v.x : v.y;
            }
        }
    }
}

// ---------------- sub-split (4-row) interleaved cluster decode loop ----------------
// smem float offsets:
#define W2S_OFF  0        // 32768  packed Uw slice (ull view) — shared
#define HDA_OFF  32768    // 4096   sub A h (dup): 2 par x 1024 ull ([k 0..255][r 0..3])
#define HDB_OFF  36864    // 4096
#define ZP_OFF   40960    // 2048   z partials (1024 ull: [kq][r][p]) — shared (per-phase life)
#define WOS_OFF  43008    // 1536   Wo slice [ul][v] — shared
#define EPP_OFF  44544    // 512    [r 0..3][128] — shared (per-phase life)
#define PPP_OFF  45056    // 512
#define PINA_OFF 45568    // 336    sub A plog inbox: 7 slots x 48
#define PINB_OFF 45904    // 336
#define PLGA_OFF 46240    // 192    sub A local plog [r 0..3][48]
#define PLGB_OFF 46432    // 192
#define BOS_OFF  46624    // 48
#define CTA_OFF  46672    // 4      sub A ctrl words (rows 0..3)
#define CTB_OFF  46676    // 4
#define MB_OFF   46680    // 12     6 mbars: HAa,HAb,PA, HBa,HBb,PB
#define SMEMF    46692
#define SMEMB    (SMEMF * 4)   // 186768 bytes

#define HB_BYTES 1024
#define PL_BYTES 192
#define EXP_H    (7 * HB_BYTES)
#define EXP_P    (7 * PL_BYTES)

__device__ __forceinline__ void do_phase(
    int s, int sub, int tid, u32 q, int grp, u32 smbase, float* smf,
    float* __restrict__ out, float& c_reg, int& hai, int ts)
{
    const ull* w2u = (const ull*)(smf + W2S_OFF);
    ull* zpu = (ull*)(smf + ZP_OFF);
    float* epp = smf + EPP_OFF;
    float* ppp = smf + PPP_OFF;
    float* WoS = smf + WOS_OFF;
    float* bos = smf + BOS_OFF;
    u32 hd_off  = sub ? (u32)HDB_OFF  : (u32)HDA_OFF;
    u32 pin_off = sub ? (u32)PINB_OFF : (u32)PINA_OFF;
    u32 plg_off = sub ? (u32)PLGB_OFF : (u32)PLGA_OFF;
    u32 ct_off  = sub ? (u32)CTB_OFF  : (u32)CTA_OFF;
    float* pin = smf + pin_off;
    float* plg = smf + plg_off;
    ull*   hd  = (ull*)(smf + hd_off);
    u32 mbb = smbase + MB_OFF * 4 + (u32)sub * 24;
    u32 mbHa = mbb, mbHb = mbb + 8, mbP = mbb + 16;
    int base = sub * 4;
    bool owner = (((int)q >> 2) == sub);
    int lane = tid - 256;
    u32 mbH_cur  = (s & 1) ? mbHb : mbHa;
    u32 mbH_next = ((s + 1) & 1) ? mbHb : mbHa;

    if (tid < 256) {
        if (tid == 0) {
            if (owner) mbar_expect_(mbP, EXP_P);
            if (s + 1 < Sn) mbar_expect_(mbH_next, EXP_H);
        }
        if (s > 0) mbar_wait_(mbH_cur, (u32)(((s - 1) >> 1) & 1));

        // ---- z: 128 gate-cols (64 ull) x 4 rows, split-k(4) ----
        int p = tid & 63, kq = tid >> 6;
        const ull* wt = w2u + kq * 4096 + p;
        const ulonglong2* hp = (const ulonglong2*)(hd + (s & 1) * 1024 + kq * 256);
        ull a0 = 0, a1 = 0, a2 = 0, a3 = 0;
#pragma unroll 8
        for (int kk = 0; kk < 32; kk++) {
            ull w = wt[kk * 64];
            ulonglong2 h01 = hp[kk * 2], h23 = hp[kk * 2 + 1];
            ffma2(a0, h01.x, w); ffma2(a1, h01.y, w);
            ffma2(a2, h23.x, w); ffma2(a3, h23.y, w);
        }
        // mid-z: spin on LOCAL ctrl word + prefetch ep (warps 0-3) / pp (warps 4-7)
        {
            int wrp = tid >> 5;
            int rrow = wrp & 3;
            int c4 = (tid & 31) * 4;
            u32 ct_addr = smbase + ct_off * 4 + (u32)rrow * 4;
            u32 w;
            do { w = ld_vol_sh(ct_addr); } while ((int)(w >> 12) < s);
            int tgt = (int)(w & 63u), adjv = (int)((w >> 6) & 63u);
            if (wrp < 4) {
                __pipeline_memcpy_async(&epp[rrow * 128 + c4],
                    &g_embP[((int)q * Vn + tgt) * 128 + c4], 16);
            } else {
                __pipeline_memcpy_async(&ppp[rrow * 128 + c4],
                    &g_proj[((((size_t)(grp * CL + (int)q) * 8 + (base + rrow)) * Tn + adjv) * 128) + c4], 16);
            }
            __pipeline_commit();
        }
#pragma unroll 8
        for (int kk = 32; kk < 64; kk++) {
            ull w = wt[kk * 64];
            ulonglong2 h01 = hp[kk * 2], h23 = hp[kk * 2 + 1];
            ffma2(a0, h01.x, w); ffma2(a1, h01.y, w);
            ffma2(a2, h23.x, w); ffma2(a3, h23.y, w);
        }
        __pipeline_wait_prior(0);
        {
            ull* zd = zpu + kq * 256 + p;
            zd[0] = a0; zd[64] = a1; zd[128] = a2; zd[192] = a3;
        }
    }
    __syncthreads();   // (a)

    // ---- pointwise (tid<128: unit u = tid>>2, row r = tid&3) ----
    if (tid < 128) {
        int u = tid >> 2, r = tid & 3;
        const ull* zb = zpu + r * 64 + 2 * u;
        ulonglong2 k0 = *(const ulonglong2*)(zb);
        ulonglong2 k1 = *(const ulonglong2*)(zb + 256);
        ulonglong2 k2 = *(const ulonglong2*)(zb + 512);
        ulonglong2 k3 = *(const ulonglong2*)(zb + 768);
        ull s0 = add2(add2(k0.x, k1.x), add2(k2.x, k3.x));
        ull s1 = add2(add2(k0.y, k1.y), add2(k2.y, k3.y));
        float4 ep = *(const float4*)&epp[r * 128 + 4 * u];
        float4 pq = *(const float4*)&ppp[r * 128 + 4 * u];
        float2 zif = unpack2(s0);
        float2 zgo = unpack2(s1);
        float zi = zif.x + ep.x + pq.x;
        float zf = zif.y + ep.y + pq.y;
        float zg = zgo.x + ep.z + pq.z;
        float zo = zgo.y + ep.w + pq.w;
        float c2 = sigm(zf) * c_reg + sigm(zi) * tanhf(zg);
        float h2v = sigm(zo) * tanhf(c2);
        c_reg = c2;
        hd[((s + 1) & 1) * 1024 + (32 * (int)q + u) * 4 + r] = pack2(h2v, h2v);
    }
    __syncthreads();   // (b)

    // ---- ctrl warp: broadcast h(s+1) via bulk DSMEM (1 KB x 7 peers) ----
    if (tid >= 256 && lane < 7 && s + 1 < Sn) {
        FENCE_ASYNC();
        u32 d = (q + 1 + (u32)lane) & 7u;
        u32 off = hd_off * 4 + (((s + 1) & 1) * 1024 + (int)q * 128) * 8;
        bulk_dsmem_(mapa_(smbase + off, d), smbase + off, HB_BYTES,
                    mapa_(mbH_next, d));
        BULK_COMMIT();
    }
    // ---- workers: partial logits into local plg ----
    if (tid < 256) {
        int v = tid & 63, rr = tid >> 6;   // rr 0..3
        if (v < Vn) {
            const float* hdupf = (const float*)(hd + ((s + 1) & 1) * 1024);
            float pa = 0.f;
#pragma unroll 8
            for (int ul = 0; ul < 32; ul++)
                pa += hdupf[((32 * (int)q + ul) * 4 + rr) * 2] * WoS[ul * Vn + v];
            plg[rr * 48 + v] = pa;
        }
    }
    __syncthreads();   // (c)

    if (tid >= 256) {
        // ---- send plog rows to their owners (4 target CTAs, skip self) ----
        if (lane < 4) {
            int tq = base + lane;            // owner CTA of sub-row 'lane'
            if (tq != (int)q) {
                FENCE_ASYNC();
                u32 slot = ((int)q < tq) ? q : q - 1u;
                u32 dst_off = pin_off * 4 + slot * PL_BYTES;
                u32 src_off = plg_off * 4 + (u32)lane * PL_BYTES;
                bulk_dsmem_(mapa_(smbase + dst_off, (u32)tq), smbase + src_off, PL_BYTES,
                            mapa_(mbP, (u32)tq));
                BULK_COMMIT();
            }
        }
        if (owner) {
            // ---- wait partials, reduce + argmax + publish ctrl for row grp*8+q ----
            mbar_wait_(mbP, (u32)(s & 1));
            int myrr = (int)q - base;
            float sA, sB = 0.f;
            {
                float sum = bos[lane];
#pragma unroll
                for (int qq = 0; qq < CL; qq++)
                    sum += (qq == (int)q) ? plg[myrr * 48 + lane]
                                          : pin[((qq < (int)q) ? qq : qq - 1) * 48 + lane];
                sA = sum;
            }
            if (lane < 16) {
                int v2 = lane + 32;
                float sum = bos[v2];
#pragma unroll
                for (int qq = 0; qq < CL; qq++)
                    sum += (qq == (int)q) ? plg[myrr * 48 + v2]
                                          : pin[((qq < (int)q) ? qq : qq - 1) * 48 + v2];
                sB = sum;
            }
            float bv = sA; int bi = lane;
            if (lane < 16) { if (sB > bv) { bv = sB; bi = lane + 32; } }
#pragma unroll
            for (int off = 16; off; off >>= 1) {
                float ov = __shfl_xor_sync(0xffffffffu, bv, off);
                int   oi = __shfl_xor_sync(0xffffffffu, bi, off);
                if (ov > bv || (ov == bv && oi < bi)) { bv = ov; bi = oi; }
            }
            int preds = bi;
            int res = (hai == ts) ? 0 : preds;
            int row = grp * 8 + (int)q;
            if (lane == 0) out[row * Sn + s] = (float)res;
            int inc = (preds == 2 && hai < ts) ? 1 : 0;
            hai += inc;
            int adjn = (hai < ts) ? hai : hai - 1;
            u32 word = ((u32)(s + 1) << 12) | ((u32)adjn << 6) | (u32)preds;
            if (lane < 8 && s + 1 < Sn)
                stc_u32(smbase + ct_off * 4 + (u32)myrr * 4, lane, word);
        }
    }
}

__global__ void __launch_bounds__(NTHR, 1) __cluster_dims__(CL, 1, 1)
k_loop(const float* __restrict__ Wo, const float* __restrict__ bo,
       float* __restrict__ out) {
    extern __shared__ __align__(16) float smf[];
    int tid = threadIdx.x;
    u32 q; asm("mov.u32 %0, %%cluster_ctarank;" : "=r"(q));
    int grp = blockIdx.x >> 3;
    if (grp >= NG) return;   // dummy clusters (grid padded >=148)
    u32 smbase = smem_u32(smf);

    // ---- init ----
    {
        const float* wsrc = g_wC + (size_t)q * 32768;
        for (int i = tid * 4; i < 32768; i += NTHR * 4)
            __pipeline_memcpy_async(&smf[W2S_OFF + i], &wsrc[i], 16);
        __pipeline_commit();
        for (int i = tid; i < 1536; i += NTHR) smf[WOS_OFF + i] = Wo[q * 1536 + i];
        if (tid < Vn) smf[BOS_OFF + tid] = bo[tid];
        ull* hdA = (ull*)(smf + HDA_OFF);
        ull* hdB = (ull*)(smf + HDB_OFF);
        for (int i = tid; i < 2048; i += NTHR) { hdA[i] = 0ull; hdB[i] = 0ull; }
        if (tid < 4) {
            ((volatile u32*)(smf + CTA_OFF))[tid] = 1u;   // tag 0, adj 0, tgt BOS
            ((volatile u32*)(smf + CTB_OFF))[tid] = 1u;
        }
        if (tid == 0) {
            u32 mb = smbase + MB_OFF * 4;
            mbar_init_(mb + 0, 1);  mbar_init_(mb + 8, 1);  mbar_init_(mb + 16, 1);
            mbar_init_(mb + 24, 1); mbar_init_(mb + 32, 1); mbar_init_(mb + 40, 1);
        }
        __pipeline_wait_prior(0);
        __syncthreads();
        asm volatile("barrier.cluster.arrive.aligned;" ::: "memory");
        asm volatile("barrier.cluster.wait.aligned;" ::: "memory");
    }

    float cA = 0.f, cB = 0.f;       // LSTM c state: (unit, row) for sub A / sub B
    int hai = 0, ts = 0;
    if (tid >= 256) ts = g_ts[grp * 8 + (int)q];

    for (int s = 0; s < Sn; s++) {
        do_phase(s, 0, tid, q, grp, smbase, smf, out, cA, hai, ts);
        do_phase(s, 1, tid, q, grp, smbase, smf, out, cB, hai, ts);
    }

    // ---- teardown: drain bulk source reads, then cluster exit ----
    if (tid >= 256) BULK_WAIT_READ0();
    asm volatile("barrier.cluster.arrive.aligned;" ::: "memory");
    asm volatile("barrier.cluster.wait.aligned;" ::: "memory");
}

// ---------------- launch ----------------
extern "C" void kernel_launch(void* const* d_in, const int* in_sizes, int n_in,
                              void* d_out, int out_size) {
    (void)in_sizes; (void)n_in; (void)out_size;
    const float* inputs   = (const float*)d_in[0];
    const int*   word_ids = (const int*)d_in[1];
    const float* embed    = (const float*)d_in[2];
    const float* W        = (const float*)d_in[3];
    const float* Uw       = (const float*)d_in[4];
    const float* bias     = (const float*)d_in[5];
    const float* Wo       = (const float*)d_in[6];
    const float* bo       = (const float*)d_in[7];
    float* out = (float*)d_out;

    static int attr_done = 0;
    if (!attr_done) {
        cudaFuncSetAttribute(k_loop, cudaFuncAttributeMaxDynamicSharedMemorySize, SMEMB);
        attr_done = 1;
    }
    k_nop<<<1, 32>>>();
    k_prep<<<1217, 256>>>(word_ids, embed, W, bias, Uw);
    k_proj<<<dim3(8, 64), 256>>>(inputs, W);
    k_loop<<<NGRID, NTHR, SMEMB>>>(Wo, bo, out);
}